// round 1
// baseline (speedup 1.0000x reference)
#include <cuda_runtime.h>
#include <cstdint>

#define L_DIM 4800
#define S_DIM 4800
#define C_DIM 256
#define INV_SCALE 0.0390625f   /* (1/sqrt(C))^2 / TEMPERATURE = 10/256 */
#define THR 0.2f

#define BM 128
#define BN 128
#define BK 16
#define AS_STRIDE 132          /* padded, keeps rows 16B-aligned (132*4=528) */

/* scratch (N=2 fixed by the problem) */
__device__ float    g_rowsum[2 * L_DIM];
__device__ float    g_colsum[2 * S_DIM];
__device__ unsigned g_colmax[2 * S_DIM];

__device__ __forceinline__ void ffma2(unsigned long long& d,
                                      unsigned long long a,
                                      unsigned long long b) {
    asm("fma.rn.f32x2 %0, %1, %2, %0;" : "+l"(d) : "l"(a), "l"(b));
}
__device__ __forceinline__ unsigned long long pack2_dup(float f) {
    unsigned long long d;
    asm("mov.b64 %0, {%1, %1};" : "=l"(d) : "f"(f));
    return d;
}

__global__ void init_kernel(int total) {
    int i = blockIdx.x * blockDim.x + threadIdx.x;
    if (i < total) {
        g_rowsum[i] = 0.f;
        g_colsum[i] = 0.f;
        g_colmax[i] = 0u;
    }
}

__global__ __launch_bounds__(256) void gemm_kernel(
    const float* __restrict__ f0, const float* __restrict__ f1,
    float* __restrict__ conf)
{
    __shared__ float As[BK][AS_STRIDE];
    __shared__ float Bs[BK][AS_STRIDE];
    __shared__ float cs[BN];

    const int n  = blockIdx.z;
    const int by = blockIdx.y;       /* l tile */
    const int bx = blockIdx.x;       /* s tile */
    const int tid = threadIdx.x;
    const int tx = tid & 15, ty = tid >> 4;

    const float* A = f0 + (size_t)n * L_DIM * C_DIM;
    const float* B = f1 + (size_t)n * S_DIM * C_DIM;

    const int lr = tid >> 2;             /* 0..63 */
    const int lk = (tid & 3) << 2;       /* 0,4,8,12 */

    unsigned long long acc[4][8];
#pragma unroll
    for (int p = 0; p < 4; p++)
#pragma unroll
        for (int j = 0; j < 8; j++) acc[p][j] = 0ull;

    float4 pa[2], pb[2];
    /* prefetch k-tile 0 */
#pragma unroll
    for (int it = 0; it < 2; it++) {
        int row = lr + it * 64;
        int gm = by * BM + row;
        int gn = bx * BN + row;
        pa[it] = (gm < L_DIM) ? *(const float4*)&A[(size_t)gm * C_DIM + lk]
                              : make_float4(0.f, 0.f, 0.f, 0.f);
        pb[it] = (gn < S_DIM) ? *(const float4*)&B[(size_t)gn * C_DIM + lk]
                              : make_float4(0.f, 0.f, 0.f, 0.f);
    }

    for (int kt = 0; kt < C_DIM / BK; kt++) {
#pragma unroll
        for (int it = 0; it < 2; it++) {
            int row = lr + it * 64;
            As[lk + 0][row] = pa[it].x; As[lk + 1][row] = pa[it].y;
            As[lk + 2][row] = pa[it].z; As[lk + 3][row] = pa[it].w;
            Bs[lk + 0][row] = pb[it].x; Bs[lk + 1][row] = pb[it].y;
            Bs[lk + 2][row] = pb[it].z; Bs[lk + 3][row] = pb[it].w;
        }
        __syncthreads();

        if (kt + 1 < C_DIM / BK) {
            int k0 = (kt + 1) * BK;
#pragma unroll
            for (int it = 0; it < 2; it++) {
                int row = lr + it * 64;
                int gm = by * BM + row;
                int gn = bx * BN + row;
                pa[it] = (gm < L_DIM) ? *(const float4*)&A[(size_t)gm * C_DIM + k0 + lk]
                                      : make_float4(0.f, 0.f, 0.f, 0.f);
                pb[it] = (gn < S_DIM) ? *(const float4*)&B[(size_t)gn * C_DIM + k0 + lk]
                                      : make_float4(0.f, 0.f, 0.f, 0.f);
            }
        }

#pragma unroll
        for (int kk = 0; kk < BK; kk++) {
            const float* arow = &As[kk][ty * 8];
            const float* brow = &Bs[kk][tx * 8];
            /* a: 8 consecutive floats -> 4 natural f32x2 pairs (LDS.128) */
            ulonglong2 a01 = *(const ulonglong2*)&arow[0];
            ulonglong2 a23 = *(const ulonglong2*)&arow[4];
            unsigned long long ap[4] = {a01.x, a01.y, a23.x, a23.y};
            float4 b03 = *(const float4*)&brow[0];
            float4 b47 = *(const float4*)&brow[4];
            unsigned long long bd[8];
            bd[0] = pack2_dup(b03.x); bd[1] = pack2_dup(b03.y);
            bd[2] = pack2_dup(b03.z); bd[3] = pack2_dup(b03.w);
            bd[4] = pack2_dup(b47.x); bd[5] = pack2_dup(b47.y);
            bd[6] = pack2_dup(b47.z); bd[7] = pack2_dup(b47.w);
#pragma unroll
            for (int j = 0; j < 8; j++) {
                ffma2(acc[0][j], ap[0], bd[j]);
                ffma2(acc[1][j], ap[1], bd[j]);
                ffma2(acc[2][j], ap[2], bd[j]);
                ffma2(acc[3][j], ap[3], bd[j]);
            }
        }
        __syncthreads();
    }

    /* ---- epilogue: store sim, accumulate exp-sums ---- */
    if (tid < BN) cs[tid] = 0.f;
    __syncthreads();

    const int l0 = by * BM + ty * 8;
    const int s0 = bx * BN + tx * 8;
    const bool s_ok = (s0 < S_DIM);
    float* crow_base = conf + (size_t)n * L_DIM * S_DIM;

    float cacc[8];
#pragma unroll
    for (int j = 0; j < 8; j++) cacc[j] = 0.f;

#pragma unroll
    for (int rr = 0; rr < 8; rr++) {
        const int p = rr >> 1, hf = rr & 1;
        float v[8];
#pragma unroll
        for (int j = 0; j < 8; j++) {
            unsigned u = hf ? (unsigned)(acc[p][j] >> 32) : (unsigned)acc[p][j];
            v[j] = __uint_as_float(u) * INV_SCALE;
        }
        const int l = l0 + rr;
        const bool l_ok = (l < L_DIM);
        float rsum = 0.f;
        if (l_ok && s_ok) {
            float* dst = crow_base + (size_t)l * S_DIM + s0;
            *(float4*)(dst + 0) = make_float4(v[0], v[1], v[2], v[3]);
            *(float4*)(dst + 4) = make_float4(v[4], v[5], v[6], v[7]);
#pragma unroll
            for (int j = 0; j < 8; j++) {
                float e = __expf(v[j]);
                rsum += e;
                cacc[j] += e;
            }
        }
        /* reduce rsum across the 16 tx-lanes of this row */
#pragma unroll
        for (int off = 1; off < 16; off <<= 1)
            rsum += __shfl_xor_sync(0xffffffffu, rsum, off);
        if (tx == 0 && l_ok)
            atomicAdd(&g_rowsum[n * L_DIM + l], rsum);
    }

    if (s_ok) {
#pragma unroll
        for (int j = 0; j < 8; j++) atomicAdd(&cs[tx * 8 + j], cacc[j]);
    }
    __syncthreads();
    if (tid < BN) {
        int s = bx * BN + tid;
        if (s < S_DIM) atomicAdd(&g_colsum[n * S_DIM + s], cs[tid]);
    }
}

__global__ void recip_kernel(int total) {
    int i = blockIdx.x * blockDim.x + threadIdx.x;
    if (i < total) {
        g_rowsum[i] = 1.f / g_rowsum[i];
        g_colsum[i] = 1.f / g_colsum[i];
    }
}

/* in-place: sim -> conf = exp(2*sim)*invR*invC, fused per-column max */
__global__ __launch_bounds__(256) void conf_kernel(float* __restrict__ conf) {
    const int n = blockIdx.z;
    const int c = blockIdx.x * 256 + threadIdx.x;
    if (c >= S_DIM) return;
    const float inv_c = g_colsum[n * S_DIM + c];
    const float* __restrict__ invr = &g_rowsum[n * L_DIM];
    const int r0 = blockIdx.y * 300;
    size_t base = ((size_t)n * L_DIM + r0) * S_DIM + c;
    unsigned cmax = 0u;
#pragma unroll 4
    for (int i = 0; i < 300; i++) {
        float sim = conf[base];
        float cf = __expf(2.f * sim) * (invr[r0 + i] * inv_c);
        conf[base] = cf;
        unsigned b = __float_as_uint(cf);
        cmax = (b > cmax) ? b : cmax;
        base += S_DIM;
    }
    atomicMax(&g_colmax[n * S_DIM + c], cmax);
}

__global__ __launch_bounds__(256) void match_kernel(
    const float* __restrict__ conf,
    float* __restrict__ out_match, float* __restrict__ out_j,
    float* __restrict__ out_mconf,
    const int* __restrict__ w0c, const int* __restrict__ w1c)
{
    __shared__ float rowv[S_DIM];
    __shared__ float red[256];
    __shared__ int minidx;

    const int l = blockIdx.x % L_DIM;
    const int n = blockIdx.x / L_DIM;
    const int tid = threadIdx.x;
    const float* cr = conf + ((size_t)n * L_DIM + l) * S_DIM;

    float m = 0.f;
    for (int s = tid; s < S_DIM; s += 256) {
        float v = cr[s];
        rowv[s] = v;
        m = fmaxf(m, v);
    }
    red[tid] = m;
    __syncthreads();
    for (int off = 128; off > 0; off >>= 1) {
        if (tid < off) red[tid] = fmaxf(red[tid], red[tid + off]);
        __syncthreads();
    }
    const float rmax = red[0];
    if (tid == 0) minidx = S_DIM;
    __syncthreads();

    const int w0 = *w0c;
    const int w1 = *w1c;
    /* border: only FIRST bd rows/cols masked (faithful to reference) */
    const bool v0 = ((l / w0) >= 2) && ((l % w0) >= 2);
    if (v0) {
        const unsigned* cm = &g_colmax[n * S_DIM];
        for (int s = tid; s < S_DIM; s += 256) {
            float v = rowv[s];
            if (v > THR && v == rmax &&
                __float_as_uint(v) == cm[s] &&
                (s / w1) >= 2 && (s % w1) >= 2)
                atomicMin(&minidx, s);
        }
    }
    __syncthreads();
    if (tid == 0) {
        const int idx = n * L_DIM + l;
        const bool match = (minidx < S_DIM);
        out_match[idx] = match ? 1.f : 0.f;
        out_j[idx]     = match ? (float)minidx : 0.f;
        out_mconf[idx] = match ? rowv[minidx] : 0.f;
    }
}

extern "C" void kernel_launch(void* const* d_in, const int* in_sizes, int n_in,
                              void* d_out, int out_size) {
    const float* f0 = (const float*)d_in[0];
    const float* f1 = (const float*)d_in[1];
    const int* w0c = (const int*)d_in[3];
    const int* w1c = (const int*)d_in[5];

    const int N = in_sizes[0] / (L_DIM * C_DIM);   /* = 2 */

    float* conf = (float*)d_out;
    const size_t nls = (size_t)N * L_DIM * S_DIM;
    float* out_match = conf + nls;
    float* out_j     = out_match + (size_t)N * L_DIM;
    float* out_mconf = out_j + (size_t)N * L_DIM;

    const int nl = N * L_DIM;
    init_kernel<<<(nl + 255) / 256, 256>>>(nl);

    dim3 ggrid((S_DIM + BN - 1) / BN, (L_DIM + BM - 1) / BM, N);
    gemm_kernel<<<ggrid, 256>>>(f0, f1, conf);

    recip_kernel<<<(nl + 255) / 256, 256>>>(nl);

    dim3 cgrid((S_DIM + 255) / 256, 16, N);   /* 16 * 300 = 4800 rows */
    conf_kernel<<<cgrid, 256>>>(conf);

    match_kernel<<<N * L_DIM, 256>>>(conf, out_match, out_j, out_mconf, w0c, w1c);
}